// round 3
// baseline (speedup 1.0000x reference)
#include <cuda_runtime.h>
#include <math.h>

#define N_ANCH 21840
#define NTILE  342            // ceil(21840/64)
#define NSTATE 683            // ceil(21840/32), 2 bits per box
#define NBLK   86             // ceil(21840/256)
#define CAP    192            // max higher-key suppressors stored per box
#define NMS_THF 0.3f
#define CLS_THF 0.05f
#define FIN_THF 0.5f
#define FULLM 0xFFFFFFFFu

// ---- static device scratch ----
__device__ float g_x1[N_ANCH], g_y1[N_ANCH], g_x2[N_ANCH], g_y2[N_ANCH];
__device__ float g_sc[N_ANCH], g_area[N_ANCH];
__device__ unsigned long long g_key64[N_ANCH];
__device__ float g_tminx1[NTILE], g_tminy1[NTILE], g_tmaxx2[NTILE], g_tmaxy2[NTILE];
__device__ float g_tamin[NTILE], g_tamax[NTILE];
__device__ unsigned short g_nbr[(size_t)N_ANCH * CAP];
__device__ int g_ncnt[N_ANCH];
__device__ unsigned long long g_state[NSTATE];

struct InPtrs { const float* cls[6]; const float* reg[6]; };

// ---------------- K1: decode (bit-exact vs reference) ----------------
__global__ void k_decode(InPtrs in) {
    int i = blockIdx.x * blockDim.x + threadIdx.x;
    if (i >= N_ANCH) return;
    const int offs[7]   = {0, 16384, 20480, 21504, 21760, 21824, 21840};
    const int maps[6]   = {128, 64, 32, 16, 8, 4};
    const float strd[6] = {4.f, 8.f, 16.f, 32.f, 64.f, 128.f};
    int sc = 0;
    #pragma unroll
    for (int k = 0; k < 5; k++) if (i >= offs[k + 1]) sc = k + 1;
    int local = i - offs[sc];
    int W = maps[sc];
    int y = local / W, x = local - y * W;
    int HW = W * W;
    const float* cls = in.cls[sc];
    const float* reg = in.reg[sc];

    float c0 = cls[local], c1 = cls[HW + local];
    float m  = fmaxf(c0, c1);
    float e0 = expf(__fsub_rn(c0, m));
    float e1 = expf(__fsub_rn(c1, m));
    float prob = __fdiv_rn(e1, __fadd_rn(e0, e1));

    float s   = strd[sc];
    float pwh = s * 4.0f;
    float pcx = __fadd_rn(0.5f * s, __fmul_rn((float)x, s));
    float pcy = __fadd_rn(0.5f * s, __fmul_rn((float)y, s));
    float l0 = reg[local], l1 = reg[HW + local];
    float l2 = reg[2 * HW + local], l3 = reg[3 * HW + local];
    float cx = __fadd_rn(pcx, __fmul_rn(__fmul_rn(l0, 0.1f), pwh));
    float cy = __fadd_rn(pcy, __fmul_rn(__fmul_rn(l1, 0.1f), pwh));
    float w  = __fmul_rn(pwh, expf(__fmul_rn(l2, 0.2f)));
    float h  = __fmul_rn(pwh, expf(__fmul_rn(l3, 0.2f)));
    float x1 = __fsub_rn(cx, __fmul_rn(w, 0.5f));
    float y1 = __fsub_rn(cy, __fmul_rn(h, 0.5f));
    float x2 = __fadd_rn(x1, w);
    float y2 = __fadd_rn(y1, h);

    g_x1[i] = x1; g_y1[i] = y1; g_x2[i] = x2; g_y2[i] = y2; g_sc[i] = prob;
    g_area[i] = __fmul_rn(__fadd_rn(__fsub_rn(x2, x1), 1.0f),
                          __fadd_rn(__fsub_rn(y2, y1), 1.0f));

    // comparable key: ascending == (descending score, ascending index).
    // invalid boxes get UINT64_MAX so they never win a key comparison.
    unsigned u   = __float_as_uint(prob);
    unsigned ord = (u & 0x80000000u) ? ~u : (u | 0x80000000u);
    unsigned long long key = ((unsigned long long)(~ord) << 16) | (unsigned)i;
    g_key64[i] = (prob > CLS_THF) ? key : 0xFFFFFFFFFFFFFFFFull;
}

// ---------------- tile bounding boxes (index order) ----------------
__global__ void k_tilebb() {
    __shared__ float m0[64], m1[64], m2[64], m3[64], m4[64], m5[64];
    int t = threadIdx.x;
    int j = blockIdx.x * 64 + t;
    bool on = j < N_ANCH;
    float a = on ? g_area[j] : 0.f;
    m0[t] = on ? g_x1[j] :  1e30f;
    m1[t] = on ? g_y1[j] :  1e30f;
    m2[t] = on ? g_x2[j] : -1e30f;
    m3[t] = on ? g_y2[j] : -1e30f;
    m4[t] = on ? a :  1e30f;
    m5[t] = on ? a : -1e30f;
    for (int s = 32; s > 0; s >>= 1) {
        __syncthreads();
        if (t < s) {
            m0[t] = fminf(m0[t], m0[t + s]);
            m1[t] = fminf(m1[t], m1[t + s]);
            m2[t] = fmaxf(m2[t], m2[t + s]);
            m3[t] = fmaxf(m3[t], m3[t + s]);
            m4[t] = fminf(m4[t], m4[t + s]);
            m5[t] = fmaxf(m5[t], m5[t + s]);
        }
    }
    if (t == 0) {
        g_tminx1[blockIdx.x] = m0[0]; g_tminy1[blockIdx.x] = m1[0];
        g_tmaxx2[blockIdx.x] = m2[0]; g_tmaxy2[blockIdx.x] = m3[0];
        g_tamin[blockIdx.x]  = m4[0]; g_tamax[blockIdx.x]  = m5[0];
    }
}

// ---------------- sparse higher-key suppressor lists (warp per box) ----------------
__global__ void k_nbr() {
    int warp = (blockIdx.x * blockDim.x + threadIdx.x) >> 5;
    int lane = threadIdx.x & 31;
    if (warp >= N_ANCH) return;
    int i = warp;
    float sci = g_sc[i];
    if (sci <= CLS_THF) { if (lane == 0) g_ncnt[i] = 0; return; }
    float x1 = g_x1[i], y1 = g_y1[i], x2 = g_x2[i], y2 = g_y2[i], ai = g_area[i];
    unsigned long long ki = g_key64[i];
    int cnt = 0;
    for (int tb = 0; tb < NTILE; tb += 32) {
        int t = tb + lane;
        bool act = false;
        if (t < NTILE) {
            float bw = __fadd_rn(__fsub_rn(fminf(x2, g_tmaxx2[t]), fmaxf(x1, g_tminx1[t])), 1.0f);
            float bh = __fadd_rn(__fsub_rn(fminf(y2, g_tmaxy2[t]), fmaxf(y1, g_tminy1[t])), 1.0f);
            float lo = fminf(ai, g_tamax[t]);
            float hi = fmaxf(ai, g_tamin[t]);
            act = (bw > 0.f) && (bh > 0.f) && (lo > 0.299f * hi);  // conservative
        }
        unsigned bal = __ballot_sync(FULLM, act);
        while (bal) {
            int tt = __ffs(bal) - 1;
            bal &= bal - 1;
            int j0 = (tb + tt) << 6;
            #pragma unroll
            for (int h = 0; h < 2; h++) {
                int j = j0 + h * 32 + lane;
                bool hit = false;
                if (j < N_ANCH) {
                    float xx1 = fmaxf(x1, g_x1[j]);
                    float yy1 = fmaxf(y1, g_y1[j]);
                    float xx2 = fminf(x2, g_x2[j]);
                    float yy2 = fminf(y2, g_y2[j]);
                    float w  = fmaxf(__fadd_rn(__fsub_rn(xx2, xx1), 1.f), 0.f);
                    float hh = fmaxf(__fadd_rn(__fsub_rn(yy2, yy1), 1.f), 0.f);
                    float inter = __fmul_rn(w, hh);
                    float aj = g_area[j];
                    if (inter > 0.299f * fmaxf(ai, aj)) {          // conservative prefilter
                        if (g_key64[j] < ki) {                     // only lower-key side pays the div
                            float iou = __fdiv_rn(inter, __fsub_rn(__fadd_rn(ai, aj), inter));
                            hit = iou > NMS_THF;
                        }
                    }
                }
                unsigned hb = __ballot_sync(FULLM, hit);
                if (hit) {
                    int off = cnt + __popc(hb & ((1u << lane) - 1));
                    if (off < CAP) g_nbr[(size_t)i * CAP + off] = (unsigned short)j;
                }
                cnt += __popc(hb);
            }
        }
    }
    if (lane == 0) g_ncnt[i] = min(cnt, CAP);
}

// ---------------- parallel fixed-point NMS resolve ----------------
// state addressed by ORIGINAL index: bit0 = resolved, bit1 = kept
__global__ void __launch_bounds__(1024) k_resolve() {
    __shared__ unsigned long long state[NSTATE];
    __shared__ int more;
    int t = threadIdx.x;
    for (int w = t; w < NSTATE; w += 1024) {
        unsigned long long sw = 0;
        int base = w << 5;
        for (int b = 0; b < 32; b++) {
            int i = base + b;
            bool valid = (i < N_ANCH) && (g_sc[i] > CLS_THF);
            if (!valid) sw |= 1ull << (2 * b);   // invalid => resolved, not kept
        }
        state[w] = sw;
    }
    if (t == 0) more = 0;
    __syncthreads();

    for (;;) {
        int lm = 0;
        for (int i = t; i < N_ANCH; i += 1024) {
            unsigned long long sv = state[i >> 5] >> ((i & 31) * 2);
            if (sv & 1ull) continue;   // resolved
            int cn = g_ncnt[i];
            const unsigned short* lst = g_nbr + (size_t)i * CAP;
            bool anyk = false, allres = true;
            for (int e = 0; e < cn; e++) {
                int c = lst[e];
                unsigned long long cs = state[c >> 5] >> ((c & 31) * 2);
                if (cs & 2ull) { anyk = true; break; }   // kept higher nbr => removed
                if (!(cs & 1ull)) allres = false;
            }
            if (anyk)
                atomicOr(&state[i >> 5], 1ull << ((i & 31) * 2));
            else if (allres)
                atomicOr(&state[i >> 5], 3ull << ((i & 31) * 2));
            else
                lm = 1;
        }
        if (lm) more = 1;
        __syncthreads();
        int m = more;
        __syncthreads();
        if (!m) break;
        if (t == 0) more = 0;
        __syncthreads();
    }
    for (int w = t; w < NSTATE; w += 1024) g_state[w] = state[w];
}

// ---------------- final masked write ----------------
__global__ void k_final(float* __restrict__ out) {
    int i = blockIdx.x * blockDim.x + threadIdx.x;
    if (i >= N_ANCH) return;
    float sc = g_sc[i];
    unsigned long long sv = g_state[i >> 5] >> ((i & 31) * 2);
    bool kp = ((sv >> 1) & 1ull) && (sc > FIN_THF);
    float f = kp ? 1.0f : 0.0f;
    out[i * 5 + 0] = __fmul_rn(g_x1[i], f);
    out[i * 5 + 1] = __fmul_rn(g_y1[i], f);
    out[i * 5 + 2] = __fmul_rn(g_x2[i], f);
    out[i * 5 + 3] = __fmul_rn(g_y2[i], f);
    out[i * 5 + 4] = __fmul_rn(sc, f);
}

extern "C" void kernel_launch(void* const* d_in, const int* in_sizes, int n_in,
                              void* d_out, int out_size) {
    (void)in_sizes; (void)n_in; (void)out_size;
    InPtrs p;
    for (int i = 0; i < 6; i++) {
        p.cls[i] = (const float*)d_in[2 * i];
        p.reg[i] = (const float*)d_in[2 * i + 1];
    }
    k_decode<<<NBLK, 256>>>(p);
    k_tilebb<<<NTILE, 64>>>();
    k_nbr<<<(N_ANCH * 32 + 255) / 256, 256>>>();
    k_resolve<<<1, 1024>>>();
    k_final<<<NBLK, 256>>>((float*)d_out);
}